// round 14
// baseline (speedup 1.0000x reference)
#include <cuda_runtime.h>
#include <cuda_fp16.h>
#include <cstdint>
#include <math.h>

// ---------------- problem constants ----------------
#define BATCH   16
#define HH      56
#define WW      56
#define DIM     384
#define HID     1536
#define WS      7
#define NWIN    1024
#define TSEQ    49
#define MTOK    50176
#define LN_EPS  1e-5f

// ---------------- device scratch ----------------
__device__ __align__(16) float  g_xB  [ (size_t)MTOK * DIM ];
__device__ __align__(16) float  g_xr  [ (size_t)MTOK * DIM ];
__device__ __align__(16) __half g_xwh [ (size_t)MTOK * DIM ];
__device__ __align__(16) __half g_hh  [ (size_t)MTOK * DIM ];
__device__ __align__(16) __half g_l2h [ (size_t)MTOK * DIM ];
__device__ __align__(16) __half g_hidh[ (size_t)MTOK * HID ];
__device__ __align__(16) __half g_Bmt [ DIM * DIM ];
__device__ __align__(16) __half g_Cmt [ DIM * DIM ];
__device__ __align__(16) __half g_At  [ DIM * DIM ];   // A^T [n][k] half
__device__ __align__(16) __half g_W1t [ (size_t)HID * DIM ];
__device__ __align__(16) __half g_W2t [ (size_t)DIM * HID ];

// ---------------- transpose + fp32->fp16 for weights ----------------
__global__ __launch_bounds__(256)
void transpose_h(const float* __restrict__ W, __half* __restrict__ Wt, int K, int N)
{
    __shared__ float tile[32][33];
    const int k0 = blockIdx.y * 32, n0 = blockIdx.x * 32;
    const int tx = threadIdx.x & 31, ty = threadIdx.x >> 5;
#pragma unroll
    for (int i = 0; i < 32; i += 8)
        tile[ty + i][tx] = W[(size_t)(k0 + ty + i) * N + n0 + tx];
    __syncthreads();
#pragma unroll
    for (int i = 0; i < 32; i += 8)
        Wt[(size_t)(n0 + ty + i) * K + k0 + tx] = __float2half_rn(tile[tx][ty + i]);
}

// ---------------- LayerNorm (warp per token) -> half, optional window remap ----------------
__global__ __launch_bounds__(256)
void ln_kernel(const float* __restrict__ x, const float* __restrict__ gw,
               const float* __restrict__ gb, __half* __restrict__ out, int remap)
{
    const int warp = threadIdx.x >> 5;
    const int lane = threadIdx.x & 31;
    const int token = blockIdx.x * 8 + warp;

    const float4* row = reinterpret_cast<const float4*>(x + (size_t)token * DIM);
    float4 v[3];
    float sum = 0.f, sq = 0.f;
#pragma unroll
    for (int q = 0; q < 3; q++) {
        v[q] = row[lane + 32 * q];
        sum += v[q].x + v[q].y + v[q].z + v[q].w;
        sq  += v[q].x * v[q].x + v[q].y * v[q].y + v[q].z * v[q].z + v[q].w * v[q].w;
    }
#pragma unroll
    for (int o = 16; o > 0; o >>= 1) {
        sum += __shfl_xor_sync(0xffffffffu, sum, o);
        sq  += __shfl_xor_sync(0xffffffffu, sq, o);
    }
    const float mu  = sum * (1.f / DIM);
    const float inv = rsqrtf(sq * (1.f / DIM) - mu * mu + LN_EPS);

    int orow = token;
    if (remap) {
        const int b   = token / (HH * WW);
        const int rem = token - b * (HH * WW);
        const int h   = rem / WW;
        const int w   = rem - h * WW;
        const int n   = b * 64 + (h / WS) * 8 + (w / WS);
        const int t   = (h % WS) * WS + (w % WS);
        orow = n * TSEQ + t;
    }
    __half* op = out + (size_t)orow * DIM;
    const float4* gw4 = reinterpret_cast<const float4*>(gw);
    const float4* gb4 = reinterpret_cast<const float4*>(gb);
#pragma unroll
    for (int q = 0; q < 3; q++) {
        const int c4 = lane + 32 * q;
        const float4 wv = gw4[c4];
        const float4 bv = gb4[c4];
        float rx = (v[q].x - mu) * inv * wv.x + bv.x;
        float ry = (v[q].y - mu) * inv * wv.y + bv.y;
        float rz = (v[q].z - mu) * inv * wv.z + bv.z;
        float rw = (v[q].w - mu) * inv * wv.w + bv.w;
        *reinterpret_cast<__half2*>(op + c4 * 4)     = __floats2half2_rn(rx, ry);
        *reinterpret_cast<__half2*>(op + c4 * 4 + 2) = __floats2half2_rn(rz, rw);
    }
}

// ---------------- MMA helpers ----------------
__device__ __forceinline__ void ldsm_x4(uint32_t& r0, uint32_t& r1, uint32_t& r2, uint32_t& r3, uint32_t addr)
{
    asm volatile("ldmatrix.sync.aligned.m8n8.x4.shared.b16 {%0,%1,%2,%3}, [%4];"
                 : "=r"(r0), "=r"(r1), "=r"(r2), "=r"(r3) : "r"(addr));
}
__device__ __forceinline__ void ldsm_x2(uint32_t& r0, uint32_t& r1, uint32_t addr)
{
    asm volatile("ldmatrix.sync.aligned.m8n8.x2.shared.b16 {%0,%1}, [%2];"
                 : "=r"(r0), "=r"(r1) : "r"(addr));
}
__device__ __forceinline__ void mma16816(float& c0, float& c1, float& c2, float& c3,
                                         uint32_t a0, uint32_t a1, uint32_t a2, uint32_t a3,
                                         uint32_t b0, uint32_t b1)
{
    asm volatile("mma.sync.aligned.m16n8k16.row.col.f32.f16.f16.f32 "
                 "{%0,%1,%2,%3}, {%4,%5,%6,%7}, {%8,%9}, {%0,%1,%2,%3};"
                 : "+f"(c0), "+f"(c1), "+f"(c2), "+f"(c3)
                 : "r"(a0), "r"(a1), "r"(a2), "r"(a3), "r"(b0), "r"(b1));
}
__device__ __forceinline__ void cp_async16(uint32_t dst, const void* src)
{
    asm volatile("cp.async.cg.shared.global [%0], [%1], 16;" :: "r"(dst), "l"(src));
}
__device__ __forceinline__ void cp_commit()
{
    asm volatile("cp.async.commit_group;");
}
template<int N> __device__ __forceinline__ void cp_wait()
{
    asm volatile("cp.async.wait_group %0;" :: "n"(N));
}

// ---------------- tensor-core scan: h_t = xB_t + h_{t-1} @ A ----------------
// 32 blocks x 32 windows. 8 warps, warp wn owns 48-col n-slice.
// h in smem (32 x 392). A^T streamed in 6 k-chunks of 64, 3-stage cp.async ring.
#define SPITCH 72
#define SBUFH  (DIM * SPITCH)
#define HPITCH 392
#define SCAN_SMEM ((3 * SBUFH + 32 * HPITCH) * 2)

__global__ __launch_bounds__(256)
void scan_mma(const float* __restrict__ xB, const __half* __restrict__ At,
              __half* __restrict__ hout)
{
    extern __shared__ __half smem[];
    __half* sH = smem + 3 * SBUFH;

    const int tid  = threadIdx.x;
    const int lane = tid & 31;
    const int wn   = tid >> 5;
    const int gr   = lane >> 2, tg = lane & 3;
    const int n0   = blockIdx.x * 32;

    const uint32_t sAbase = (uint32_t)__cvta_generic_to_shared(smem);
    const uint32_t sHbase = (uint32_t)__cvta_generic_to_shared(sH);

    const uint32_t hOff = (uint32_t)(((((lane >> 3) & 1) * 8 + (lane & 7)) * HPITCH + (lane >> 4) * 8) * 2);
    const uint32_t bOff = (uint32_t)(((wn * 48 + (lane & 7)) * SPITCH + ((lane >> 3) & 1) * 8) * 2);

    const int colb = wn * 48 + tg * 2;
    // windows per thread: mi tile 0: n0+gr, n0+gr+8; mi tile 1: +16, +24
    const float* xBp[4];
    __half* hop[4];
#pragma unroll
    for (int q = 0; q < 4; q++) {
        const int w = n0 + (q >> 1) * 16 + (q & 1) * 8 + gr;
        xBp[q] = xB + (size_t)w * TSEQ * DIM;
        hop[q] = hout + (size_t)w * TSEQ * DIM;
    }

    auto issue = [&](int c, int b) {
        const uint32_t dbase = sAbase + (uint32_t)b * (SBUFH * 2);
#pragma unroll
        for (int i = 0; i < 12; i++) {
            const int idx = i * 256 + tid;
            const int row = idx >> 3, seg = idx & 7;
            cp_async16(dbase + (uint32_t)(row * SPITCH + seg * 8) * 2,
                       At + (size_t)row * DIM + c * 64 + seg * 8);
        }
        cp_commit();
    };

    issue(0, 0);
    issue(1, 1);
    int nxt = 2;

    float acc[2][6][4];

    // ---- t = 0: h = xB ----
#pragma unroll
    for (int mi = 0; mi < 2; mi++)
#pragma unroll
    for (int ni = 0; ni < 6; ni++) {
        const float2 a = *reinterpret_cast<const float2*>(xBp[mi * 2]     + colb + ni * 8);
        const float2 b = *reinterpret_cast<const float2*>(xBp[mi * 2 + 1] + colb + ni * 8);
        acc[mi][ni][0] = a.x; acc[mi][ni][1] = a.y; acc[mi][ni][2] = b.x; acc[mi][ni][3] = b.y;
        const __half2 h0 = __floats2half2_rn(a.x, a.y);
        const __half2 h1 = __floats2half2_rn(b.x, b.y);
        *reinterpret_cast<__half2*>(&sH[(mi * 16 + gr) * HPITCH + colb + ni * 8])     = h0;
        *reinterpret_cast<__half2*>(&sH[(mi * 16 + gr + 8) * HPITCH + colb + ni * 8]) = h1;
        *reinterpret_cast<__half2*>(hop[mi * 2]     + colb + ni * 8) = h0;
        *reinterpret_cast<__half2*>(hop[mi * 2 + 1] + colb + ni * 8) = h1;
    }

    for (int t = 1; t < TSEQ; t++) {
#pragma unroll
        for (int mi = 0; mi < 2; mi++)
#pragma unroll
        for (int ni = 0; ni < 6; ni++) {
            const float2 a = *reinterpret_cast<const float2*>(xBp[mi * 2]     + (size_t)t * DIM + colb + ni * 8);
            const float2 b = *reinterpret_cast<const float2*>(xBp[mi * 2 + 1] + (size_t)t * DIM + colb + ni * 8);
            acc[mi][ni][0] = a.x; acc[mi][ni][1] = a.y; acc[mi][ni][2] = b.x; acc[mi][ni][3] = b.y;
        }

        for (int cc = 0; cc < 6; cc++) {
            const int cur = nxt - 2;
            cp_wait<1>();
            __syncthreads();
            issue(nxt % 6, nxt % 3);
            nxt++;
            const uint32_t bufB = sAbase + (uint32_t)(cur % 3) * (SBUFH * 2) + bOff;
#pragma unroll
            for (int kt = 0; kt < 4; kt++) {
                uint32_t a0[4], a1[4];
                ldsm_x4(a0[0], a0[1], a0[2], a0[3], sHbase + hOff + (uint32_t)(cc * 4 + kt) * 32);
                ldsm_x4(a1[0], a1[1], a1[2], a1[3], sHbase + hOff + (uint32_t)(cc * 4 + kt) * 32 + 16 * HPITCH * 2);
#pragma unroll
                for (int ni = 0; ni < 6; ni++) {
                    uint32_t b0, b1;
                    ldsm_x2(b0, b1, bufB + (uint32_t)(ni * 8 * SPITCH * 2) + (uint32_t)kt * 32);
                    mma16816(acc[0][ni][0], acc[0][ni][1], acc[0][ni][2], acc[0][ni][3],
                             a0[0], a0[1], a0[2], a0[3], b0, b1);
                    mma16816(acc[1][ni][0], acc[1][ni][1], acc[1][ni][2], acc[1][ni][3],
                             a1[0], a1[1], a1[2], a1[3], b0, b1);
                }
            }
        }
        __syncthreads();
#pragma unroll
        for (int mi = 0; mi < 2; mi++)
#pragma unroll
        for (int ni = 0; ni < 6; ni++) {
            const __half2 h0 = __floats2half2_rn(acc[mi][ni][0], acc[mi][ni][1]);
            const __half2 h1 = __floats2half2_rn(acc[mi][ni][2], acc[mi][ni][3]);
            if (t + 1 < TSEQ) {
                *reinterpret_cast<__half2*>(&sH[(mi * 16 + gr) * HPITCH + colb + ni * 8])     = h0;
                *reinterpret_cast<__half2*>(&sH[(mi * 16 + gr + 8) * HPITCH + colb + ni * 8]) = h1;
            }
            *reinterpret_cast<__half2*>(hop[mi * 2]     + (size_t)t * DIM + colb + ni * 8) = h0;
            *reinterpret_cast<__half2*>(hop[mi * 2 + 1] + (size_t)t * DIM + colb + ni * 8) = h1;
        }
    }
    cp_wait<0>();
}

// ---------------- fp16 tensor-core GEMM, 256x128 tile, 512 threads, BK=64, 3 stages ----------------
#define EPI_NONE    0
#define EPI_WINREV  1
#define EPI_GELU    2
#define EPI_BIASRES 3

#define GP      72                          // halfs per smem row
#define GA_H    (256 * GP)                  // A halfs per stage
#define GB_H    (128 * GP)                  // B halfs per stage
#define GSTG_B  ((GA_H + GB_H) * 2)         // bytes per stage = 55296
#define GEMM_SMEM (3 * GSTG_B)              // 165888

__device__ __forceinline__ float gelu_exact(float v)
{
    return 0.5f * v * (1.f + erff(v * 0.70710678118654752f));
}

template<int EPI>
__global__ __launch_bounds__(512)
void gemm_h(const __half* __restrict__ Ag, const __half* __restrict__ Bg,
            const float* __restrict__ bias, const float* __restrict__ res,
            void* __restrict__ Cv, int M, int N, int K)
{
    extern __shared__ __align__(16) __half gsm[];

    const int tid  = threadIdx.x;
    const int lane = tid & 31;
    const int wid  = tid >> 5;
    const int wm   = wid & 3;           // 0..3 -> m band of 64
    const int wn   = wid >> 2;          // 0..3 -> n band of 32
    const int m0   = blockIdx.y * 256;
    const int n0   = blockIdx.x * 128;

    const uint32_t smB = (uint32_t)__cvta_generic_to_shared(gsm);

    auto load_stage = [&](int kt, int stg) {
        const uint32_t base = smB + (uint32_t)stg * GSTG_B;
        const size_t ko = (size_t)kt * 64;
#pragma unroll
        for (int i = 0; i < 4; i++) {           // A: 2048 chunks / 512 threads
            const int c = i * 512 + tid;
            const int r = c >> 3, s = c & 7;
            cp_async16(base + (uint32_t)(r * GP + s * 8) * 2,
                       Ag + (size_t)(m0 + r) * K + ko + s * 8);
        }
#pragma unroll
        for (int i = 0; i < 2; i++) {           // B: 1024 chunks / 512 threads
            const int c = i * 512 + tid;
            const int r = c >> 3, s = c & 7;
            cp_async16(base + GA_H * 2 + (uint32_t)(r * GP + s * 8) * 2,
                       Bg + (size_t)(n0 + r) * K + ko + s * 8);
        }
        cp_commit();
    };

    // ldmatrix lane addresses (byte offsets within a stage)
    const uint32_t aOff = (uint32_t)(((wm * 64 + ((lane >> 3) & 1) * 8 + (lane & 7)) * GP + (lane >> 4) * 8) * 2);
    const uint32_t bOff = (uint32_t)(((wn * 32 + ((lane >> 4) & 1) * 8 + (lane & 7)) * GP + ((lane >> 3) & 1) * 8) * 2);

    float acc[4][4][4];
#pragma unroll
    for (int mi = 0; mi < 4; mi++)
#pragma unroll
        for (int ni = 0; ni < 4; ni++)
#pragma unroll
            for (int q = 0; q < 4; q++) acc[mi][ni][q] = 0.f;

    const int NK = K >> 6;
    load_stage(0, 0);
    load_stage(1, 1);

    for (int kt = 0; kt < NK; kt++) {
        if (kt + 1 < NK) cp_wait<1>(); else cp_wait<0>();
        __syncthreads();
        if (kt + 2 < NK) load_stage(kt + 2, (kt + 2) % 3);

        const uint32_t stgB = smB + (uint32_t)(kt % 3) * GSTG_B;
        const uint32_t aB = stgB + aOff;
        const uint32_t bB = stgB + GA_H * 2 + bOff;
#pragma unroll
        for (int kk = 0; kk < 4; kk++) {
            uint32_t a[4][4], bf[4][2];
#pragma unroll
            for (int mi = 0; mi < 4; mi++)
                ldsm_x4(a[mi][0], a[mi][1], a[mi][2], a[mi][3],
                        aB + kk * 32 + (uint32_t)(mi * 16 * GP * 2));
#pragma unroll
            for (int nj = 0; nj < 2; nj++)
                ldsm_x4(bf[nj * 2][0], bf[nj * 2][1], bf[nj * 2 + 1][0], bf[nj * 2 + 1][1],
                        bB + kk * 32 + (uint32_t)(nj * 16 * GP * 2));
#pragma unroll
            for (int mi = 0; mi < 4; mi++)
#pragma unroll
                for (int ni = 0; ni < 4; ni++)
                    mma16816(acc[mi][ni][0], acc[mi][ni][1], acc[mi][ni][2], acc[mi][ni][3],
                             a[mi][0], a[mi][1], a[mi][2], a[mi][3], bf[ni][0], bf[ni][1]);
        }
    }

    // ---------------- epilogue ----------------
    const int gr = lane >> 2, tg = lane & 3;

    float2 bias2[4];
    if (EPI == EPI_GELU || EPI == EPI_BIASRES) {
#pragma unroll
        for (int ni = 0; ni < 4; ni++)
            bias2[ni] = *reinterpret_cast<const float2*>(bias + n0 + wn * 32 + ni * 8 + tg * 2);
    }

#pragma unroll
    for (int mi = 0; mi < 4; mi++)
#pragma unroll
    for (int rh = 0; rh < 2; rh++) {
        const int gm = m0 + wm * 64 + mi * 16 + rh * 8 + gr;
        int orow = gm;
        if (EPI == EPI_WINREV) {
            const int n = gm / TSEQ;
            const int t = gm - n * TSEQ;
            const int b = n >> 6;
            const int rm = n & 63;
            const int wh = rm >> 3, wwi = rm & 7;
            const int ti = t / WS, tj = t - ti * WS;
            orow = (b * HH + wh * WS + ti) * WW + wwi * WS + tj;
        }
#pragma unroll
        for (int ni = 0; ni < 4; ni++) {
            const int col = n0 + wn * 32 + ni * 8 + tg * 2;
            float v0 = acc[mi][ni][rh * 2];
            float v1 = acc[mi][ni][rh * 2 + 1];
            if (EPI == EPI_GELU) {
                v0 = gelu_exact(v0 + bias2[ni].x);
                v1 = gelu_exact(v1 + bias2[ni].y);
                __half* C = (__half*)Cv;
                *reinterpret_cast<__half2*>(C + (size_t)orow * N + col) = __floats2half2_rn(v0, v1);
            } else {
                if (EPI == EPI_BIASRES) {
                    const float2 r = *reinterpret_cast<const float2*>(res + (size_t)gm * N + col);
                    v0 += bias2[ni].x + r.x;
                    v1 += bias2[ni].y + r.y;
                }
                float* C = (float*)Cv;
                float2 o; o.x = v0; o.y = v1;
                *reinterpret_cast<float2*>(C + (size_t)orow * N + col) = o;
            }
        }
    }
}

// ---------------- launch ----------------
extern "C" void kernel_launch(void* const* d_in, const int* in_sizes, int n_in,
                              void* d_out, int out_size)
{
    const float* x    = (const float*)d_in[0];
    const float* A    = (const float*)d_in[1];
    const float* Bm   = (const float*)d_in[2];
    const float* Cm   = (const float*)d_in[3];
    const float* ln1w = (const float*)d_in[4];
    const float* ln1b = (const float*)d_in[5];
    const float* ln2w = (const float*)d_in[6];
    const float* ln2b = (const float*)d_in[7];
    const float* W1   = (const float*)d_in[8];
    const float* b1   = (const float*)d_in[9];
    const float* W2   = (const float*)d_in[10];
    const float* b2   = (const float*)d_in[11];
    float* out = (float*)d_out;

    float  *p_xB, *p_xr;
    __half *p_xwh, *p_hh, *p_l2h, *p_hidh, *p_Bmt, *p_Cmt, *p_At, *p_W1t, *p_W2t;
    cudaGetSymbolAddress((void**)&p_xB,   g_xB);
    cudaGetSymbolAddress((void**)&p_xr,   g_xr);
    cudaGetSymbolAddress((void**)&p_xwh,  g_xwh);
    cudaGetSymbolAddress((void**)&p_hh,   g_hh);
    cudaGetSymbolAddress((void**)&p_l2h,  g_l2h);
    cudaGetSymbolAddress((void**)&p_hidh, g_hidh);
    cudaGetSymbolAddress((void**)&p_Bmt,  g_Bmt);
    cudaGetSymbolAddress((void**)&p_Cmt,  g_Cmt);
    cudaGetSymbolAddress((void**)&p_At,   g_At);
    cudaGetSymbolAddress((void**)&p_W1t,  g_W1t);
    cudaGetSymbolAddress((void**)&p_W2t,  g_W2t);

    cudaFuncSetAttribute(scan_mma, cudaFuncAttributeMaxDynamicSharedMemorySize, SCAN_SMEM);
    cudaFuncSetAttribute(gemm_h<EPI_NONE>,    cudaFuncAttributeMaxDynamicSharedMemorySize, GEMM_SMEM);
    cudaFuncSetAttribute(gemm_h<EPI_WINREV>,  cudaFuncAttributeMaxDynamicSharedMemorySize, GEMM_SMEM);
    cudaFuncSetAttribute(gemm_h<EPI_GELU>,    cudaFuncAttributeMaxDynamicSharedMemorySize, GEMM_SMEM);
    cudaFuncSetAttribute(gemm_h<EPI_BIASRES>, cudaFuncAttributeMaxDynamicSharedMemorySize, GEMM_SMEM);

    // weight transposes + LN1
    transpose_h<<<dim3(DIM / 32, DIM / 32), 256>>>(Bm, p_Bmt, DIM, DIM);
    transpose_h<<<dim3(DIM / 32, DIM / 32), 256>>>(Cm, p_Cmt, DIM, DIM);
    transpose_h<<<dim3(HID / 32, DIM / 32), 256>>>(W1, p_W1t, DIM, HID);
    transpose_h<<<dim3(DIM / 32, HID / 32), 256>>>(W2, p_W2t, HID, DIM);
    ln_kernel<<<MTOK / 8, 256>>>(x, ln1w, ln1b, p_xwh, 1);

    // xB = xw @ Bm  (fp32 out, scan input)
    gemm_h<EPI_NONE><<<dim3(DIM / 128, MTOK / 256), 512, GEMM_SMEM>>>(p_xwh, p_Bmt, nullptr, nullptr, p_xB, MTOK, DIM, DIM);

    // A^T transpose (only needed by scan)
    transpose_h<<<dim3(DIM / 32, DIM / 32), 256>>>(A,  p_At,  DIM, DIM);

    // tensor-core sequential scan -> half states
    scan_mma<<<NWIN / 32, 256, SCAN_SMEM>>>(p_xB, p_At, p_hh);

    // xr = h @ Cm, fused window-reverse (fp32 out)
    gemm_h<EPI_WINREV><<<dim3(DIM / 128, MTOK / 256), 512, GEMM_SMEM>>>(p_hh, p_Cmt, nullptr, nullptr, p_xr, MTOK, DIM, DIM);

    // LN2 -> half
    ln_kernel<<<MTOK / 8, 256>>>(p_xr, ln2w, ln2b, p_l2h, 0);

    // hid = gelu(ln2 @ W1 + b1) -> half
    gemm_h<EPI_GELU><<<dim3(HID / 128, MTOK / 256), 512, GEMM_SMEM>>>(p_l2h, p_W1t, b1, nullptr, p_hidh, MTOK, HID, DIM);

    // out = xr + hid @ W2 + b2 (fp32)
    gemm_h<EPI_BIASRES><<<dim3(DIM / 128, MTOK / 256), 512, GEMM_SMEM>>>(p_hidh, p_W2t, b2, p_xr, out, MTOK, DIM, HID);
}

// round 15
// speedup vs baseline: 1.0496x; 1.0496x over previous
#include <cuda_runtime.h>
#include <cuda_fp16.h>
#include <cstdint>
#include <math.h>

// ---------------- problem constants ----------------
#define BATCH   16
#define HH      56
#define WW      56
#define DIM     384
#define HID     1536
#define WS      7
#define NWIN    1024
#define TSEQ    49
#define MTOK    50176
#define LN_EPS  1e-5f

// ---------------- device scratch ----------------
__device__ __align__(16) float  g_xB  [ (size_t)MTOK * DIM ];
__device__ __align__(16) float  g_xr  [ (size_t)MTOK * DIM ];
__device__ __align__(16) __half g_xwh [ (size_t)MTOK * DIM ];
__device__ __align__(16) __half g_hh  [ (size_t)MTOK * DIM ];
__device__ __align__(16) __half g_l2h [ (size_t)MTOK * DIM ];
__device__ __align__(16) __half g_hidh[ (size_t)MTOK * HID ];
__device__ __align__(16) __half g_Bmt [ DIM * DIM ];
__device__ __align__(16) __half g_Cmt [ DIM * DIM ];
__device__ __align__(16) __half g_At  [ DIM * DIM ];   // A^T [n][k] half
__device__ __align__(16) __half g_W1t [ (size_t)HID * DIM ];
__device__ __align__(16) __half g_W2t [ (size_t)DIM * HID ];

// ---------------- transpose + fp32->fp16 for weights ----------------
__global__ __launch_bounds__(256)
void transpose_h(const float* __restrict__ W, __half* __restrict__ Wt, int K, int N)
{
    __shared__ float tile[32][33];
    const int k0 = blockIdx.y * 32, n0 = blockIdx.x * 32;
    const int tx = threadIdx.x & 31, ty = threadIdx.x >> 5;
#pragma unroll
    for (int i = 0; i < 32; i += 8)
        tile[ty + i][tx] = W[(size_t)(k0 + ty + i) * N + n0 + tx];
    __syncthreads();
#pragma unroll
    for (int i = 0; i < 32; i += 8)
        Wt[(size_t)(n0 + ty + i) * K + k0 + tx] = __float2half_rn(tile[tx][ty + i]);
}

// ---------------- LayerNorm (warp per token) -> half, optional window remap ----------------
__global__ __launch_bounds__(256)
void ln_kernel(const float* __restrict__ x, const float* __restrict__ gw,
               const float* __restrict__ gb, __half* __restrict__ out, int remap)
{
    const int warp = threadIdx.x >> 5;
    const int lane = threadIdx.x & 31;
    const int token = blockIdx.x * 8 + warp;

    const float4* row = reinterpret_cast<const float4*>(x + (size_t)token * DIM);
    float4 v[3];
    float sum = 0.f, sq = 0.f;
#pragma unroll
    for (int q = 0; q < 3; q++) {
        v[q] = row[lane + 32 * q];
        sum += v[q].x + v[q].y + v[q].z + v[q].w;
        sq  += v[q].x * v[q].x + v[q].y * v[q].y + v[q].z * v[q].z + v[q].w * v[q].w;
    }
#pragma unroll
    for (int o = 16; o > 0; o >>= 1) {
        sum += __shfl_xor_sync(0xffffffffu, sum, o);
        sq  += __shfl_xor_sync(0xffffffffu, sq, o);
    }
    const float mu  = sum * (1.f / DIM);
    const float inv = rsqrtf(sq * (1.f / DIM) - mu * mu + LN_EPS);

    int orow = token;
    if (remap) {
        const int b   = token / (HH * WW);
        const int rem = token - b * (HH * WW);
        const int h   = rem / WW;
        const int w   = rem - h * WW;
        const int n   = b * 64 + (h / WS) * 8 + (w / WS);
        const int t   = (h % WS) * WS + (w % WS);
        orow = n * TSEQ + t;
    }
    __half* op = out + (size_t)orow * DIM;
    const float4* gw4 = reinterpret_cast<const float4*>(gw);
    const float4* gb4 = reinterpret_cast<const float4*>(gb);
#pragma unroll
    for (int q = 0; q < 3; q++) {
        const int c4 = lane + 32 * q;
        const float4 wv = gw4[c4];
        const float4 bv = gb4[c4];
        float rx = (v[q].x - mu) * inv * wv.x + bv.x;
        float ry = (v[q].y - mu) * inv * wv.y + bv.y;
        float rz = (v[q].z - mu) * inv * wv.z + bv.z;
        float rw = (v[q].w - mu) * inv * wv.w + bv.w;
        *reinterpret_cast<__half2*>(op + c4 * 4)     = __floats2half2_rn(rx, ry);
        *reinterpret_cast<__half2*>(op + c4 * 4 + 2) = __floats2half2_rn(rz, rw);
    }
}

// ---------------- MMA helpers ----------------
__device__ __forceinline__ void ldsm_x4(uint32_t& r0, uint32_t& r1, uint32_t& r2, uint32_t& r3, uint32_t addr)
{
    asm volatile("ldmatrix.sync.aligned.m8n8.x4.shared.b16 {%0,%1,%2,%3}, [%4];"
                 : "=r"(r0), "=r"(r1), "=r"(r2), "=r"(r3) : "r"(addr));
}
__device__ __forceinline__ void ldsm_x2(uint32_t& r0, uint32_t& r1, uint32_t addr)
{
    asm volatile("ldmatrix.sync.aligned.m8n8.x2.shared.b16 {%0,%1}, [%2];"
                 : "=r"(r0), "=r"(r1) : "r"(addr));
}
__device__ __forceinline__ void mma16816(float& c0, float& c1, float& c2, float& c3,
                                         uint32_t a0, uint32_t a1, uint32_t a2, uint32_t a3,
                                         uint32_t b0, uint32_t b1)
{
    asm volatile("mma.sync.aligned.m16n8k16.row.col.f32.f16.f16.f32 "
                 "{%0,%1,%2,%3}, {%4,%5,%6,%7}, {%8,%9}, {%0,%1,%2,%3};"
                 : "+f"(c0), "+f"(c1), "+f"(c2), "+f"(c3)
                 : "r"(a0), "r"(a1), "r"(a2), "r"(a3), "r"(b0), "r"(b1));
}
__device__ __forceinline__ void cp_async16(uint32_t dst, const void* src)
{
    asm volatile("cp.async.cg.shared.global [%0], [%1], 16;" :: "r"(dst), "l"(src));
}
__device__ __forceinline__ void cp_commit()
{
    asm volatile("cp.async.commit_group;");
}
template<int N> __device__ __forceinline__ void cp_wait()
{
    asm volatile("cp.async.wait_group %0;" :: "n"(N));
}

// ---------------- tensor-core scan: h_t = xB_t + h_{t-1} @ A ----------------
// 32 blocks x 32 windows. 8 warps, warp wn owns 48-col n-slice.
// h in smem (32 x 392). A^T streamed in 6 k-chunks of 64, 3-stage cp.async ring.
#define SPITCH 72
#define SBUFH  (DIM * SPITCH)
#define HPITCH 392
#define SCAN_SMEM ((3 * SBUFH + 32 * HPITCH) * 2)

__global__ __launch_bounds__(256)
void scan_mma(const float* __restrict__ xB, const __half* __restrict__ At,
              __half* __restrict__ hout)
{
    extern __shared__ __half smem[];
    __half* sH = smem + 3 * SBUFH;

    const int tid  = threadIdx.x;
    const int lane = tid & 31;
    const int wn   = tid >> 5;
    const int gr   = lane >> 2, tg = lane & 3;
    const int n0   = blockIdx.x * 32;

    const uint32_t sAbase = (uint32_t)__cvta_generic_to_shared(smem);
    const uint32_t sHbase = (uint32_t)__cvta_generic_to_shared(sH);

    const uint32_t hOff = (uint32_t)(((((lane >> 3) & 1) * 8 + (lane & 7)) * HPITCH + (lane >> 4) * 8) * 2);
    const uint32_t bOff = (uint32_t)(((wn * 48 + (lane & 7)) * SPITCH + ((lane >> 3) & 1) * 8) * 2);

    const int colb = wn * 48 + tg * 2;
    const float* xBp[4];
    __half* hop[4];
#pragma unroll
    for (int q = 0; q < 4; q++) {
        const int w = n0 + (q >> 1) * 16 + (q & 1) * 8 + gr;
        xBp[q] = xB + (size_t)w * TSEQ * DIM;
        hop[q] = hout + (size_t)w * TSEQ * DIM;
    }

    auto issue = [&](int c, int b) {
        const uint32_t dbase = sAbase + (uint32_t)b * (SBUFH * 2);
#pragma unroll
        for (int i = 0; i < 12; i++) {
            const int idx = i * 256 + tid;
            const int row = idx >> 3, seg = idx & 7;
            cp_async16(dbase + (uint32_t)(row * SPITCH + seg * 8) * 2,
                       At + (size_t)row * DIM + c * 64 + seg * 8);
        }
        cp_commit();
    };

    issue(0, 0);
    issue(1, 1);
    int nxt = 2;

    float acc[2][6][4];

    // ---- t = 0: h = xB ----
#pragma unroll
    for (int mi = 0; mi < 2; mi++)
#pragma unroll
    for (int ni = 0; ni < 6; ni++) {
        const float2 a = *reinterpret_cast<const float2*>(xBp[mi * 2]     + colb + ni * 8);
        const float2 b = *reinterpret_cast<const float2*>(xBp[mi * 2 + 1] + colb + ni * 8);
        acc[mi][ni][0] = a.x; acc[mi][ni][1] = a.y; acc[mi][ni][2] = b.x; acc[mi][ni][3] = b.y;
        const __half2 h0 = __floats2half2_rn(a.x, a.y);
        const __half2 h1 = __floats2half2_rn(b.x, b.y);
        *reinterpret_cast<__half2*>(&sH[(mi * 16 + gr) * HPITCH + colb + ni * 8])     = h0;
        *reinterpret_cast<__half2*>(&sH[(mi * 16 + gr + 8) * HPITCH + colb + ni * 8]) = h1;
        *reinterpret_cast<__half2*>(hop[mi * 2]     + colb + ni * 8) = h0;
        *reinterpret_cast<__half2*>(hop[mi * 2 + 1] + colb + ni * 8) = h1;
    }

    for (int t = 1; t < TSEQ; t++) {
#pragma unroll
        for (int mi = 0; mi < 2; mi++)
#pragma unroll
        for (int ni = 0; ni < 6; ni++) {
            const float2 a = *reinterpret_cast<const float2*>(xBp[mi * 2]     + (size_t)t * DIM + colb + ni * 8);
            const float2 b = *reinterpret_cast<const float2*>(xBp[mi * 2 + 1] + (size_t)t * DIM + colb + ni * 8);
            acc[mi][ni][0] = a.x; acc[mi][ni][1] = a.y; acc[mi][ni][2] = b.x; acc[mi][ni][3] = b.y;
        }

        for (int cc = 0; cc < 6; cc++) {
            const int cur = nxt - 2;
            cp_wait<1>();
            __syncthreads();
            issue(nxt % 6, nxt % 3);
            nxt++;
            const uint32_t bufB = sAbase + (uint32_t)(cur % 3) * (SBUFH * 2) + bOff;
#pragma unroll
            for (int kt = 0; kt < 4; kt++) {
                uint32_t a0[4], a1[4];
                ldsm_x4(a0[0], a0[1], a0[2], a0[3], sHbase + hOff + (uint32_t)(cc * 4 + kt) * 32);
                ldsm_x4(a1[0], a1[1], a1[2], a1[3], sHbase + hOff + (uint32_t)(cc * 4 + kt) * 32 + 16 * HPITCH * 2);
#pragma unroll
                for (int ni = 0; ni < 6; ni++) {
                    uint32_t b0, b1;
                    ldsm_x2(b0, b1, bufB + (uint32_t)(ni * 8 * SPITCH * 2) + (uint32_t)kt * 32);
                    mma16816(acc[0][ni][0], acc[0][ni][1], acc[0][ni][2], acc[0][ni][3],
                             a0[0], a0[1], a0[2], a0[3], b0, b1);
                    mma16816(acc[1][ni][0], acc[1][ni][1], acc[1][ni][2], acc[1][ni][3],
                             a1[0], a1[1], a1[2], a1[3], b0, b1);
                }
            }
        }
        __syncthreads();
#pragma unroll
        for (int mi = 0; mi < 2; mi++)
#pragma unroll
        for (int ni = 0; ni < 6; ni++) {
            const __half2 h0 = __floats2half2_rn(acc[mi][ni][0], acc[mi][ni][1]);
            const __half2 h1 = __floats2half2_rn(acc[mi][ni][2], acc[mi][ni][3]);
            if (t + 1 < TSEQ) {
                *reinterpret_cast<__half2*>(&sH[(mi * 16 + gr) * HPITCH + colb + ni * 8])     = h0;
                *reinterpret_cast<__half2*>(&sH[(mi * 16 + gr + 8) * HPITCH + colb + ni * 8]) = h1;
            }
            *reinterpret_cast<__half2*>(hop[mi * 2]     + (size_t)t * DIM + colb + ni * 8) = h0;
            *reinterpret_cast<__half2*>(hop[mi * 2 + 1] + (size_t)t * DIM + colb + ni * 8) = h1;
        }
    }
    cp_wait<0>();
}

// ---------------- fp16 tensor-core GEMM, cp.async 3-stage pipeline, BK=64 ----------------
// C[M,N] = A[M,K] @ Bt[N,K]^T.  128x128 CTA tile, 8 warps 4x2.  (R13 winner)
#define EPI_NONE    0
#define EPI_WINREV  1
#define EPI_GELU    2
#define EPI_BIASRES 3

#define GP     72                     // halfs per smem row (64 + 8 pad)
#define GSTGH  (128 * GP)             // halfs per operand per stage
#define GEMM_SMEM (3 * 2 * GSTGH * 2) // 3 stages x (A+B) = 110592 bytes

__device__ __forceinline__ float gelu_exact(float v)
{
    return 0.5f * v * (1.f + erff(v * 0.70710678118654752f));
}

template<int EPI>
__global__ __launch_bounds__(256)
void gemm_h(const __half* __restrict__ Ag, const __half* __restrict__ Bg,
            const float* __restrict__ bias, const float* __restrict__ res,
            void* __restrict__ Cv, int M, int N, int K)
{
    extern __shared__ __align__(16) __half gsm[];

    const int tid  = threadIdx.x;
    const int lane = tid & 31;
    const int wid  = tid >> 5;
    const int wm   = wid >> 1;          // 0..3
    const int wn   = wid & 1;           // 0..1
    const int m0   = blockIdx.y * 128;
    const int n0   = blockIdx.x * 128;

    const uint32_t smB = (uint32_t)__cvta_generic_to_shared(gsm);

    const int rr[4] = { tid >> 3, (tid + 256) >> 3, (tid + 512) >> 3, (tid + 768) >> 3 };
    const int ss[4] = { tid & 7,  (tid + 256) & 7,  (tid + 512) & 7,  (tid + 768) & 7 };

    auto load_stage = [&](int kt, int stg) {
        const uint32_t base = smB + (uint32_t)stg * (2 * GSTGH * 2);
        const size_t ko = (size_t)kt * 64;
#pragma unroll
        for (int i = 0; i < 4; i++) {
            const uint32_t so = (uint32_t)(rr[i] * GP + ss[i] * 8) * 2;
            cp_async16(base + so,             Ag + (size_t)(m0 + rr[i]) * K + ko + ss[i] * 8);
            cp_async16(base + GSTGH * 2 + so, Bg + (size_t)(n0 + rr[i]) * K + ko + ss[i] * 8);
        }
        cp_commit();
    };

    const uint32_t aOff = (uint32_t)(((wm * 32 + ((lane >> 3) & 1) * 8 + (lane & 7)) * GP + (lane >> 4) * 8) * 2);
    const uint32_t bOff = (uint32_t)(((wn * 64 + ((lane >> 4) & 1) * 8 + (lane & 7)) * GP + ((lane >> 3) & 1) * 8) * 2);

    float acc[2][8][4];
#pragma unroll
    for (int mi = 0; mi < 2; mi++)
#pragma unroll
        for (int ni = 0; ni < 8; ni++)
#pragma unroll
            for (int q = 0; q < 4; q++) acc[mi][ni][q] = 0.f;

    const int NK = K >> 6;            // k-tiles of 64
    load_stage(0, 0);
    load_stage(1, 1);

    for (int kt = 0; kt < NK; kt++) {
        if (kt + 1 < NK) cp_wait<1>(); else cp_wait<0>();
        __syncthreads();
        if (kt + 2 < NK) load_stage(kt + 2, (kt + 2) % 3);

        const uint32_t stgB = smB + (uint32_t)(kt % 3) * (2 * GSTGH * 2);
        const uint32_t aB = stgB + aOff;
        const uint32_t bB = stgB + GSTGH * 2 + bOff;
#pragma unroll
        for (int kk = 0; kk < 4; kk++) {           // 4 x k16
            uint32_t a[2][4], bf[8][2];
            ldsm_x4(a[0][0], a[0][1], a[0][2], a[0][3], aB + kk * 32);
            ldsm_x4(a[1][0], a[1][1], a[1][2], a[1][3], aB + kk * 32 + 16 * GP * 2);
#pragma unroll
            for (int nj = 0; nj < 4; nj++)
                ldsm_x4(bf[nj * 2][0], bf[nj * 2][1], bf[nj * 2 + 1][0], bf[nj * 2 + 1][1],
                        bB + kk * 32 + (uint32_t)(nj * 16 * GP * 2));
#pragma unroll
            for (int mi = 0; mi < 2; mi++)
#pragma unroll
                for (int ni = 0; ni < 8; ni++)
                    mma16816(acc[mi][ni][0], acc[mi][ni][1], acc[mi][ni][2], acc[mi][ni][3],
                             a[mi][0], a[mi][1], a[mi][2], a[mi][3], bf[ni][0], bf[ni][1]);
        }
    }

    // ---------------- epilogue ----------------
    const int gr = lane >> 2, tg = lane & 3;

    float2 bias2[8];
    if (EPI == EPI_GELU || EPI == EPI_BIASRES) {
#pragma unroll
        for (int ni = 0; ni < 8; ni++)
            bias2[ni] = *reinterpret_cast<const float2*>(bias + n0 + wn * 64 + ni * 8 + tg * 2);
    }

#pragma unroll
    for (int mi = 0; mi < 2; mi++)
#pragma unroll
    for (int rh = 0; rh < 2; rh++) {
        const int gm = m0 + wm * 32 + mi * 16 + rh * 8 + gr;
        int orow = gm;
        if (EPI == EPI_WINREV) {
            const int n = gm / TSEQ;
            const int t = gm - n * TSEQ;
            const int b = n >> 6;
            const int rm = n & 63;
            const int wh = rm >> 3, wwi = rm & 7;
            const int ti = t / WS, tj = t - ti * WS;
            orow = (b * HH + wh * WS + ti) * WW + wwi * WS + tj;
        }
#pragma unroll
        for (int ni = 0; ni < 8; ni++) {
            const int col = n0 + wn * 64 + ni * 8 + tg * 2;
            float v0 = acc[mi][ni][rh * 2];
            float v1 = acc[mi][ni][rh * 2 + 1];
            if (EPI == EPI_GELU) {
                v0 = gelu_exact(v0 + bias2[ni].x);
                v1 = gelu_exact(v1 + bias2[ni].y);
                __half* C = (__half*)Cv;
                *reinterpret_cast<__half2*>(C + (size_t)orow * N + col) = __floats2half2_rn(v0, v1);
            } else {
                if (EPI == EPI_BIASRES) {
                    const float2 r = *reinterpret_cast<const float2*>(res + (size_t)gm * N + col);
                    v0 += bias2[ni].x + r.x;
                    v1 += bias2[ni].y + r.y;
                }
                float* C = (float*)Cv;
                float2 o; o.x = v0; o.y = v1;
                *reinterpret_cast<float2*>(C + (size_t)orow * N + col) = o;
            }
        }
    }
}

// ---------------- launch ----------------
extern "C" void kernel_launch(void* const* d_in, const int* in_sizes, int n_in,
                              void* d_out, int out_size)
{
    const float* x    = (const float*)d_in[0];
    const float* A    = (const float*)d_in[1];
    const float* Bm   = (const float*)d_in[2];
    const float* Cm   = (const float*)d_in[3];
    const float* ln1w = (const float*)d_in[4];
    const float* ln1b = (const float*)d_in[5];
    const float* ln2w = (const float*)d_in[6];
    const float* ln2b = (const float*)d_in[7];
    const float* W1   = (const float*)d_in[8];
    const float* b1   = (const float*)d_in[9];
    const float* W2   = (const float*)d_in[10];
    const float* b2   = (const float*)d_in[11];
    float* out = (float*)d_out;

    float  *p_xB, *p_xr;
    __half *p_xwh, *p_hh, *p_l2h, *p_hidh, *p_Bmt, *p_Cmt, *p_At, *p_W1t, *p_W2t;
    cudaGetSymbolAddress((void**)&p_xB,   g_xB);
    cudaGetSymbolAddress((void**)&p_xr,   g_xr);
    cudaGetSymbolAddress((void**)&p_xwh,  g_xwh);
    cudaGetSymbolAddress((void**)&p_hh,   g_hh);
    cudaGetSymbolAddress((void**)&p_l2h,  g_l2h);
    cudaGetSymbolAddress((void**)&p_hidh, g_hidh);
    cudaGetSymbolAddress((void**)&p_Bmt,  g_Bmt);
    cudaGetSymbolAddress((void**)&p_Cmt,  g_Cmt);
    cudaGetSymbolAddress((void**)&p_At,   g_At);
    cudaGetSymbolAddress((void**)&p_W1t,  g_W1t);
    cudaGetSymbolAddress((void**)&p_W2t,  g_W2t);

    cudaFuncSetAttribute(scan_mma, cudaFuncAttributeMaxDynamicSharedMemorySize, SCAN_SMEM);
    cudaFuncSetAttribute(gemm_h<EPI_NONE>,    cudaFuncAttributeMaxDynamicSharedMemorySize, GEMM_SMEM);
    cudaFuncSetAttribute(gemm_h<EPI_WINREV>,  cudaFuncAttributeMaxDynamicSharedMemorySize, GEMM_SMEM);
    cudaFuncSetAttribute(gemm_h<EPI_GELU>,    cudaFuncAttributeMaxDynamicSharedMemorySize, GEMM_SMEM);
    cudaFuncSetAttribute(gemm_h<EPI_BIASRES>, cudaFuncAttributeMaxDynamicSharedMemorySize, GEMM_SMEM);

    // weight transposes + LN1
    transpose_h<<<dim3(DIM / 32, DIM / 32), 256>>>(Bm, p_Bmt, DIM, DIM);
    transpose_h<<<dim3(DIM / 32, DIM / 32), 256>>>(Cm, p_Cmt, DIM, DIM);
    transpose_h<<<dim3(HID / 32, DIM / 32), 256>>>(W1, p_W1t, DIM, HID);
    transpose_h<<<dim3(DIM / 32, HID / 32), 256>>>(W2, p_W2t, HID, DIM);
    ln_kernel<<<MTOK / 8, 256>>>(x, ln1w, ln1b, p_xwh, 1);

    // xB = xw @ Bm  (fp32 out, scan input)
    gemm_h<EPI_NONE><<<dim3(DIM / 128, MTOK / 128), 256, GEMM_SMEM>>>(p_xwh, p_Bmt, nullptr, nullptr, p_xB, MTOK, DIM, DIM);

    // A^T transpose (only needed by scan)
    transpose_h<<<dim3(DIM / 32, DIM / 32), 256>>>(A,  p_At,  DIM, DIM);

    // tensor-core sequential scan -> half states (32 windows/block)
    scan_mma<<<NWIN / 32, 256, SCAN_SMEM>>>(p_xB, p_At, p_hh);

    // xr = h @ Cm, fused window-reverse (fp32 out)
    gemm_h<EPI_WINREV><<<dim3(DIM / 128, MTOK / 128), 256, GEMM_SMEM>>>(p_hh, p_Cmt, nullptr, nullptr, p_xr, MTOK, DIM, DIM);

    // LN2 -> half
    ln_kernel<<<MTOK / 8, 256>>>(p_xr, ln2w, ln2b, p_l2h, 0);

    // hid = gelu(ln2 @ W1 + b1) -> half
    gemm_h<EPI_GELU><<<dim3(HID / 128, MTOK / 128), 256, GEMM_SMEM>>>(p_l2h, p_W1t, b1, nullptr, p_hidh, MTOK, HID, DIM);

    // out = xr + hid @ W2 + b2 (fp32)
    gemm_h<EPI_BIASRES><<<dim3(DIM / 128, MTOK / 128), 256, GEMM_SMEM>>>(p_hidh, p_W2t, b2, p_xr, out, MTOK, DIM, HID);
}

// round 16
// speedup vs baseline: 1.1097x; 1.0573x over previous
#include <cuda_runtime.h>
#include <cuda_fp16.h>
#include <cstdint>
#include <math.h>

// ---------------- problem constants ----------------
#define BATCH   16
#define HH      56
#define WW      56
#define DIM     384
#define HID     1536
#define WS      7
#define NWIN    1024
#define TSEQ    49
#define MTOK    50176
#define LN_EPS  1e-5f

// ---------------- device scratch ----------------
__device__ __align__(16) float  g_xr  [ (size_t)MTOK * DIM ];
__device__ __align__(16) __half g_xBh [ (size_t)MTOK * DIM ];   // xw @ Bm (half)
__device__ __align__(16) __half g_xwh [ (size_t)MTOK * DIM ];
__device__ __align__(16) __half g_hh  [ (size_t)MTOK * DIM ];
__device__ __align__(16) __half g_l2h [ (size_t)MTOK * DIM ];
__device__ __align__(16) __half g_hidh[ (size_t)MTOK * HID ];
__device__ __align__(16) __half g_Bmt [ DIM * DIM ];
__device__ __align__(16) __half g_Cmt [ DIM * DIM ];
__device__ __align__(16) __half g_At  [ DIM * DIM ];   // A^T [n][k] half
__device__ __align__(16) __half g_W1t [ (size_t)HID * DIM ];
__device__ __align__(16) __half g_W2t [ (size_t)DIM * HID ];

// ---------------- batched weight transpose + fp32->fp16 ----------------
// tiles: [0,144) Bm  [144,288) Cm  [288,864) W1  [864,1440) W2
__global__ __launch_bounds__(256)
void transpose_weights(const float* __restrict__ Bm, const float* __restrict__ Cm,
                       const float* __restrict__ W1, const float* __restrict__ W2,
                       __half* __restrict__ Bmt, __half* __restrict__ Cmt,
                       __half* __restrict__ W1t, __half* __restrict__ W2t)
{
    __shared__ float tile[32][33];
    const int g = blockIdx.x;
    const float* src; __half* dst; int K, N, t;
    if (g < 144)      { src = Bm; dst = Bmt; K = DIM; N = DIM; t = g; }
    else if (g < 288) { src = Cm; dst = Cmt; K = DIM; N = DIM; t = g - 144; }
    else if (g < 864) { src = W1; dst = W1t; K = DIM; N = HID; t = g - 288; }
    else              { src = W2; dst = W2t; K = HID; N = DIM; t = g - 864; }
    const int ntx = N >> 5;
    const int k0 = (t / ntx) * 32, n0 = (t % ntx) * 32;
    const int tx = threadIdx.x & 31, ty = threadIdx.x >> 5;
#pragma unroll
    for (int i = 0; i < 32; i += 8)
        tile[ty + i][tx] = src[(size_t)(k0 + ty + i) * N + n0 + tx];
    __syncthreads();
#pragma unroll
    for (int i = 0; i < 32; i += 8)
        dst[(size_t)(n0 + ty + i) * K + k0 + tx] = __float2half_rn(tile[tx][ty + i]);
}

__global__ __launch_bounds__(256)
void transpose_h(const float* __restrict__ W, __half* __restrict__ Wt, int K, int N)
{
    __shared__ float tile[32][33];
    const int k0 = blockIdx.y * 32, n0 = blockIdx.x * 32;
    const int tx = threadIdx.x & 31, ty = threadIdx.x >> 5;
#pragma unroll
    for (int i = 0; i < 32; i += 8)
        tile[ty + i][tx] = W[(size_t)(k0 + ty + i) * N + n0 + tx];
    __syncthreads();
#pragma unroll
    for (int i = 0; i < 32; i += 8)
        Wt[(size_t)(n0 + ty + i) * K + k0 + tx] = __float2half_rn(tile[tx][ty + i]);
}

// ---------------- LayerNorm (warp per token) -> half, optional window remap ----------------
__global__ __launch_bounds__(256)
void ln_kernel(const float* __restrict__ x, const float* __restrict__ gw,
               const float* __restrict__ gb, __half* __restrict__ out, int remap)
{
    const int warp = threadIdx.x >> 5;
    const int lane = threadIdx.x & 31;
    const int token = blockIdx.x * 8 + warp;

    const float4* row = reinterpret_cast<const float4*>(x + (size_t)token * DIM);
    float4 v[3];
    float sum = 0.f, sq = 0.f;
#pragma unroll
    for (int q = 0; q < 3; q++) {
        v[q] = row[lane + 32 * q];
        sum += v[q].x + v[q].y + v[q].z + v[q].w;
        sq  += v[q].x * v[q].x + v[q].y * v[q].y + v[q].z * v[q].z + v[q].w * v[q].w;
    }
#pragma unroll
    for (int o = 16; o > 0; o >>= 1) {
        sum += __shfl_xor_sync(0xffffffffu, sum, o);
        sq  += __shfl_xor_sync(0xffffffffu, sq, o);
    }
    const float mu  = sum * (1.f / DIM);
    const float inv = rsqrtf(sq * (1.f / DIM) - mu * mu + LN_EPS);

    int orow = token;
    if (remap) {
        const int b   = token / (HH * WW);
        const int rem = token - b * (HH * WW);
        const int h   = rem / WW;
        const int w   = rem - h * WW;
        const int n   = b * 64 + (h / WS) * 8 + (w / WS);
        const int t   = (h % WS) * WS + (w % WS);
        orow = n * TSEQ + t;
    }
    __half* op = out + (size_t)orow * DIM;
    const float4* gw4 = reinterpret_cast<const float4*>(gw);
    const float4* gb4 = reinterpret_cast<const float4*>(gb);
#pragma unroll
    for (int q = 0; q < 3; q++) {
        const int c4 = lane + 32 * q;
        const float4 wv = gw4[c4];
        const float4 bv = gb4[c4];
        float rx = (v[q].x - mu) * inv * wv.x + bv.x;
        float ry = (v[q].y - mu) * inv * wv.y + bv.y;
        float rz = (v[q].z - mu) * inv * wv.z + bv.z;
        float rw = (v[q].w - mu) * inv * wv.w + bv.w;
        *reinterpret_cast<__half2*>(op + c4 * 4)     = __floats2half2_rn(rx, ry);
        *reinterpret_cast<__half2*>(op + c4 * 4 + 2) = __floats2half2_rn(rz, rw);
    }
}

// ---------------- MMA helpers ----------------
__device__ __forceinline__ void ldsm_x4(uint32_t& r0, uint32_t& r1, uint32_t& r2, uint32_t& r3, uint32_t addr)
{
    asm volatile("ldmatrix.sync.aligned.m8n8.x4.shared.b16 {%0,%1,%2,%3}, [%4];"
                 : "=r"(r0), "=r"(r1), "=r"(r2), "=r"(r3) : "r"(addr));
}
__device__ __forceinline__ void ldsm_x2(uint32_t& r0, uint32_t& r1, uint32_t addr)
{
    asm volatile("ldmatrix.sync.aligned.m8n8.x2.shared.b16 {%0,%1}, [%2];"
                 : "=r"(r0), "=r"(r1) : "r"(addr));
}
__device__ __forceinline__ void mma16816(float& c0, float& c1, float& c2, float& c3,
                                         uint32_t a0, uint32_t a1, uint32_t a2, uint32_t a3,
                                         uint32_t b0, uint32_t b1)
{
    asm volatile("mma.sync.aligned.m16n8k16.row.col.f32.f16.f16.f32 "
                 "{%0,%1,%2,%3}, {%4,%5,%6,%7}, {%8,%9}, {%0,%1,%2,%3};"
                 : "+f"(c0), "+f"(c1), "+f"(c2), "+f"(c3)
                 : "r"(a0), "r"(a1), "r"(a2), "r"(a3), "r"(b0), "r"(b1));
}
__device__ __forceinline__ void cp_async16(uint32_t dst, const void* src)
{
    asm volatile("cp.async.cg.shared.global [%0], [%1], 16;" :: "r"(dst), "l"(src));
}
__device__ __forceinline__ void cp_commit()
{
    asm volatile("cp.async.commit_group;");
}
template<int N> __device__ __forceinline__ void cp_wait()
{
    asm volatile("cp.async.wait_group %0;" :: "n"(N));
}

// ---------------- tensor-core scan: h_t = xB_t + h_{t-1} @ A ----------------
// 64 blocks x 16 windows (R13 winner). 8 warps, warp wn owns 48-col n-slice.
// h in smem (16 x 392). A^T streamed in 6 k-chunks of 64, 3-stage cp.async ring.
#define SPITCH 72
#define SBUFH  (DIM * SPITCH)
#define HPITCH 392
#define SCAN_SMEM ((3 * SBUFH + 16 * HPITCH) * 2)

__global__ __launch_bounds__(256)
void scan_mma(const __half* __restrict__ xB, const __half* __restrict__ At,
              __half* __restrict__ hout)
{
    extern __shared__ __half smem[];
    __half* sH = smem + 3 * SBUFH;

    const int tid  = threadIdx.x;
    const int lane = tid & 31;
    const int wn   = tid >> 5;
    const int gr   = lane >> 2, tg = lane & 3;
    const int n0   = blockIdx.x * 16;

    const uint32_t sAbase = (uint32_t)__cvta_generic_to_shared(smem);
    const uint32_t sHbase = (uint32_t)__cvta_generic_to_shared(sH);

    const uint32_t hOff = (uint32_t)(((((lane >> 3) & 1) * 8 + (lane & 7)) * HPITCH + (lane >> 4) * 8) * 2);
    const uint32_t bOff = (uint32_t)(((wn * 48 + (lane & 7)) * SPITCH + ((lane >> 3) & 1) * 8) * 2);

    const int colb = wn * 48 + tg * 2;
    const int w0 = n0 + gr, w1 = n0 + gr + 8;
    const __half* xB0 = xB + (size_t)w0 * TSEQ * DIM;
    const __half* xB1 = xB + (size_t)w1 * TSEQ * DIM;
    __half* ho0 = hout + (size_t)w0 * TSEQ * DIM;
    __half* ho1 = hout + (size_t)w1 * TSEQ * DIM;

    auto issue = [&](int c, int b) {
        const uint32_t dbase = sAbase + (uint32_t)b * (SBUFH * 2);
#pragma unroll
        for (int i = 0; i < 12; i++) {
            const int idx = i * 256 + tid;
            const int row = idx >> 3, seg = idx & 7;
            cp_async16(dbase + (uint32_t)(row * SPITCH + seg * 8) * 2,
                       At + (size_t)row * DIM + c * 64 + seg * 8);
        }
        cp_commit();
    };

    issue(0, 0);
    issue(1, 1);
    int nxt = 2;

    float acc[6][4];

    // ---- t = 0: h = xB ----
#pragma unroll
    for (int ni = 0; ni < 6; ni++) {
        const __half2 ah = *reinterpret_cast<const __half2*>(xB0 + colb + ni * 8);
        const __half2 bh = *reinterpret_cast<const __half2*>(xB1 + colb + ni * 8);
        const float2 a = __half22float2(ah);
        const float2 b = __half22float2(bh);
        acc[ni][0] = a.x; acc[ni][1] = a.y; acc[ni][2] = b.x; acc[ni][3] = b.y;
        *reinterpret_cast<__half2*>(&sH[gr * HPITCH + colb + ni * 8])       = ah;
        *reinterpret_cast<__half2*>(&sH[(gr + 8) * HPITCH + colb + ni * 8]) = bh;
        *reinterpret_cast<__half2*>(ho0 + colb + ni * 8) = ah;
        *reinterpret_cast<__half2*>(ho1 + colb + ni * 8) = bh;
    }

    for (int t = 1; t < TSEQ; t++) {
#pragma unroll
        for (int ni = 0; ni < 6; ni++) {
            const float2 a = __half22float2(*reinterpret_cast<const __half2*>(xB0 + (size_t)t * DIM + colb + ni * 8));
            const float2 b = __half22float2(*reinterpret_cast<const __half2*>(xB1 + (size_t)t * DIM + colb + ni * 8));
            acc[ni][0] = a.x; acc[ni][1] = a.y; acc[ni][2] = b.x; acc[ni][3] = b.y;
        }

        for (int cc = 0; cc < 6; cc++) {
            const int cur = nxt - 2;
            cp_wait<1>();
            __syncthreads();
            issue(nxt % 6, nxt % 3);
            nxt++;
            const uint32_t bufB = sAbase + (uint32_t)(cur % 3) * (SBUFH * 2) + bOff;
#pragma unroll
            for (int kt = 0; kt < 4; kt++) {
                uint32_t a0, a1, a2, a3;
                ldsm_x4(a0, a1, a2, a3, sHbase + hOff + (uint32_t)(cc * 4 + kt) * 32);
#pragma unroll
                for (int ni = 0; ni < 6; ni++) {
                    uint32_t b0, b1;
                    ldsm_x2(b0, b1, bufB + (uint32_t)(ni * 8 * SPITCH * 2) + (uint32_t)kt * 32);
                    mma16816(acc[ni][0], acc[ni][1], acc[ni][2], acc[ni][3],
                             a0, a1, a2, a3, b0, b1);
                }
            }
        }
        __syncthreads();
#pragma unroll
        for (int ni = 0; ni < 6; ni++) {
            const __half2 h0 = __floats2half2_rn(acc[ni][0], acc[ni][1]);
            const __half2 h1 = __floats2half2_rn(acc[ni][2], acc[ni][3]);
            if (t + 1 < TSEQ) {
                *reinterpret_cast<__half2*>(&sH[gr * HPITCH + colb + ni * 8])       = h0;
                *reinterpret_cast<__half2*>(&sH[(gr + 8) * HPITCH + colb + ni * 8]) = h1;
            }
            *reinterpret_cast<__half2*>(ho0 + (size_t)t * DIM + colb + ni * 8) = h0;
            *reinterpret_cast<__half2*>(ho1 + (size_t)t * DIM + colb + ni * 8) = h1;
        }
    }
    cp_wait<0>();
}

// ---------------- fp16 tensor-core GEMM, cp.async 3-stage pipeline, BK=64 ----------------
// C[M,N] = A[M,K] @ Bt[N,K]^T.  128x128 CTA tile, 8 warps 4x2.  (R13 winner)
#define EPI_TOHALF  0
#define EPI_WINREV  1
#define EPI_GELU    2
#define EPI_BIASRES 3

#define GP     72                     // halfs per smem row (64 + 8 pad)
#define GSTGH  (128 * GP)             // halfs per operand per stage
#define GEMM_SMEM (3 * 2 * GSTGH * 2) // 3 stages x (A+B) = 110592 bytes

__device__ __forceinline__ float gelu_exact(float v)
{
    return 0.5f * v * (1.f + erff(v * 0.70710678118654752f));
}

template<int EPI>
__global__ __launch_bounds__(256)
void gemm_h(const __half* __restrict__ Ag, const __half* __restrict__ Bg,
            const float* __restrict__ bias, const float* __restrict__ res,
            void* __restrict__ Cv, int M, int N, int K)
{
    extern __shared__ __align__(16) __half gsm[];

    const int tid  = threadIdx.x;
    const int lane = tid & 31;
    const int wid  = tid >> 5;
    const int wm   = wid >> 1;          // 0..3
    const int wn   = wid & 1;           // 0..1
    const int m0   = blockIdx.y * 128;
    const int n0   = blockIdx.x * 128;

    const uint32_t smB = (uint32_t)__cvta_generic_to_shared(gsm);

    const int rr[4] = { tid >> 3, (tid + 256) >> 3, (tid + 512) >> 3, (tid + 768) >> 3 };
    const int ss[4] = { tid & 7,  (tid + 256) & 7,  (tid + 512) & 7,  (tid + 768) & 7 };

    auto load_stage = [&](int kt, int stg) {
        const uint32_t base = smB + (uint32_t)stg * (2 * GSTGH * 2);
        const size_t ko = (size_t)kt * 64;
#pragma unroll
        for (int i = 0; i < 4; i++) {
            const uint32_t so = (uint32_t)(rr[i] * GP + ss[i] * 8) * 2;
            cp_async16(base + so,             Ag + (size_t)(m0 + rr[i]) * K + ko + ss[i] * 8);
            cp_async16(base + GSTGH * 2 + so, Bg + (size_t)(n0 + rr[i]) * K + ko + ss[i] * 8);
        }
        cp_commit();
    };

    const uint32_t aOff = (uint32_t)(((wm * 32 + ((lane >> 3) & 1) * 8 + (lane & 7)) * GP + (lane >> 4) * 8) * 2);
    const uint32_t bOff = (uint32_t)(((wn * 64 + ((lane >> 4) & 1) * 8 + (lane & 7)) * GP + ((lane >> 3) & 1) * 8) * 2);

    float acc[2][8][4];
#pragma unroll
    for (int mi = 0; mi < 2; mi++)
#pragma unroll
        for (int ni = 0; ni < 8; ni++)
#pragma unroll
            for (int q = 0; q < 4; q++) acc[mi][ni][q] = 0.f;

    const int NK = K >> 6;            // k-tiles of 64
    load_stage(0, 0);
    load_stage(1, 1);

    for (int kt = 0; kt < NK; kt++) {
        if (kt + 1 < NK) cp_wait<1>(); else cp_wait<0>();
        __syncthreads();
        if (kt + 2 < NK) load_stage(kt + 2, (kt + 2) % 3);

        const uint32_t stgB = smB + (uint32_t)(kt % 3) * (2 * GSTGH * 2);
        const uint32_t aB = stgB + aOff;
        const uint32_t bB = stgB + GSTGH * 2 + bOff;
#pragma unroll
        for (int kk = 0; kk < 4; kk++) {           // 4 x k16
            uint32_t a[2][4], bf[8][2];
            ldsm_x4(a[0][0], a[0][1], a[0][2], a[0][3], aB + kk * 32);
            ldsm_x4(a[1][0], a[1][1], a[1][2], a[1][3], aB + kk * 32 + 16 * GP * 2);
#pragma unroll
            for (int nj = 0; nj < 4; nj++)
                ldsm_x4(bf[nj * 2][0], bf[nj * 2][1], bf[nj * 2 + 1][0], bf[nj * 2 + 1][1],
                        bB + kk * 32 + (uint32_t)(nj * 16 * GP * 2));
#pragma unroll
            for (int mi = 0; mi < 2; mi++)
#pragma unroll
                for (int ni = 0; ni < 8; ni++)
                    mma16816(acc[mi][ni][0], acc[mi][ni][1], acc[mi][ni][2], acc[mi][ni][3],
                             a[mi][0], a[mi][1], a[mi][2], a[mi][3], bf[ni][0], bf[ni][1]);
        }
    }

    // ---------------- epilogue ----------------
    const int gr = lane >> 2, tg = lane & 3;

    float2 bias2[8];
    if (EPI == EPI_GELU || EPI == EPI_BIASRES) {
#pragma unroll
        for (int ni = 0; ni < 8; ni++)
            bias2[ni] = *reinterpret_cast<const float2*>(bias + n0 + wn * 64 + ni * 8 + tg * 2);
    }

#pragma unroll
    for (int mi = 0; mi < 2; mi++)
#pragma unroll
    for (int rh = 0; rh < 2; rh++) {
        const int gm = m0 + wm * 32 + mi * 16 + rh * 8 + gr;
        int orow = gm;
        if (EPI == EPI_WINREV) {
            const int n = gm / TSEQ;
            const int t = gm - n * TSEQ;
            const int b = n >> 6;
            const int rm = n & 63;
            const int wh = rm >> 3, wwi = rm & 7;
            const int ti = t / WS, tj = t - ti * WS;
            orow = (b * HH + wh * WS + ti) * WW + wwi * WS + tj;
        }
#pragma unroll
        for (int ni = 0; ni < 8; ni++) {
            const int col = n0 + wn * 64 + ni * 8 + tg * 2;
            float v0 = acc[mi][ni][rh * 2];
            float v1 = acc[mi][ni][rh * 2 + 1];
            if (EPI == EPI_GELU || EPI == EPI_TOHALF) {
                if (EPI == EPI_GELU) {
                    v0 = gelu_exact(v0 + bias2[ni].x);
                    v1 = gelu_exact(v1 + bias2[ni].y);
                }
                __half* C = (__half*)Cv;
                *reinterpret_cast<__half2*>(C + (size_t)orow * N + col) = __floats2half2_rn(v0, v1);
            } else {
                if (EPI == EPI_BIASRES) {
                    const float2 r = *reinterpret_cast<const float2*>(res + (size_t)gm * N + col);
                    v0 += bias2[ni].x + r.x;
                    v1 += bias2[ni].y + r.y;
                }
                float* C = (float*)Cv;
                float2 o; o.x = v0; o.y = v1;
                *reinterpret_cast<float2*>(C + (size_t)orow * N + col) = o;
            }
        }
    }
}

// ---------------- launch ----------------
extern "C" void kernel_launch(void* const* d_in, const int* in_sizes, int n_in,
                              void* d_out, int out_size)
{
    const float* x    = (const float*)d_in[0];
    const float* A    = (const float*)d_in[1];
    const float* Bm   = (const float*)d_in[2];
    const float* Cm   = (const float*)d_in[3];
    const float* ln1w = (const float*)d_in[4];
    const float* ln1b = (const float*)d_in[5];
    const float* ln2w = (const float*)d_in[6];
    const float* ln2b = (const float*)d_in[7];
    const float* W1   = (const float*)d_in[8];
    const float* b1   = (const float*)d_in[9];
    const float* W2   = (const float*)d_in[10];
    const float* b2   = (const float*)d_in[11];
    float* out = (float*)d_out;

    float  *p_xr;
    __half *p_xBh, *p_xwh, *p_hh, *p_l2h, *p_hidh, *p_Bmt, *p_Cmt, *p_At, *p_W1t, *p_W2t;
    cudaGetSymbolAddress((void**)&p_xr,   g_xr);
    cudaGetSymbolAddress((void**)&p_xBh,  g_xBh);
    cudaGetSymbolAddress((void**)&p_xwh,  g_xwh);
    cudaGetSymbolAddress((void**)&p_hh,   g_hh);
    cudaGetSymbolAddress((void**)&p_l2h,  g_l2h);
    cudaGetSymbolAddress((void**)&p_hidh, g_hidh);
    cudaGetSymbolAddress((void**)&p_Bmt,  g_Bmt);
    cudaGetSymbolAddress((void**)&p_Cmt,  g_Cmt);
    cudaGetSymbolAddress((void**)&p_At,   g_At);
    cudaGetSymbolAddress((void**)&p_W1t,  g_W1t);
    cudaGetSymbolAddress((void**)&p_W2t,  g_W2t);

    cudaFuncSetAttribute(scan_mma, cudaFuncAttributeMaxDynamicSharedMemorySize, SCAN_SMEM);
    cudaFuncSetAttribute(gemm_h<EPI_TOHALF>,  cudaFuncAttributeMaxDynamicSharedMemorySize, GEMM_SMEM);
    cudaFuncSetAttribute(gemm_h<EPI_WINREV>,  cudaFuncAttributeMaxDynamicSharedMemorySize, GEMM_SMEM);
    cudaFuncSetAttribute(gemm_h<EPI_GELU>,    cudaFuncAttributeMaxDynamicSharedMemorySize, GEMM_SMEM);
    cudaFuncSetAttribute(gemm_h<EPI_BIASRES>, cudaFuncAttributeMaxDynamicSharedMemorySize, GEMM_SMEM);

    // 0: batched weight transposes; 1: A^T; 2: LN1
    transpose_weights<<<1440, 256>>>(Bm, Cm, W1, W2, p_Bmt, p_Cmt, p_W1t, p_W2t);
    transpose_h<<<dim3(DIM / 32, DIM / 32), 256>>>(A, p_At, DIM, DIM);
    ln_kernel<<<MTOK / 8, 256>>>(x, ln1w, ln1b, p_xwh, 1);

    // 3: xB = xw @ Bm (half out)
    gemm_h<EPI_TOHALF><<<dim3(DIM / 128, MTOK / 128), 256, GEMM_SMEM>>>(p_xwh, p_Bmt, nullptr, nullptr, p_xBh, MTOK, DIM, DIM);

    // 4: tensor-core sequential scan -> half states (16 windows/block)
    scan_mma<<<NWIN / 16, 256, SCAN_SMEM>>>(p_xBh, p_At, p_hh);

    // 5: xr = h @ Cm, fused window-reverse (fp32 out)  [ncu -s 5 profiles this]
    gemm_h<EPI_WINREV><<<dim3(DIM / 128, MTOK / 128), 256, GEMM_SMEM>>>(p_hh, p_Cmt, nullptr, nullptr, p_xr, MTOK, DIM, DIM);

    // 6: LN2 -> half
    ln_kernel<<<MTOK / 8, 256>>>(p_xr, ln2w, ln2b, p_l2h, 0);

    // 7: hid = gelu(ln2 @ W1 + b1) -> half
    gemm_h<EPI_GELU><<<dim3(HID / 128, MTOK / 128), 256, GEMM_SMEM>>>(p_l2h, p_W1t, b1, nullptr, p_hidh, MTOK, HID, DIM);

    // 8: out = xr + hid @ W2 + b2 (fp32)
    gemm_h<EPI_BIASRES><<<dim3(DIM / 128, MTOK / 128), 256, GEMM_SMEM>>>(p_hidh, p_W2t, b2, p_xr, out, MTOK, DIM, HID);
}